// round 5
// baseline (speedup 1.0000x reference)
#include <cuda_runtime.h>
#include <cuda_fp16.h>
#include <cstdint>

// ============================================================================
// DiagonalMahalanobisDistance: x[8192,512], y[8192,512], log_scale[512] (fp32)
// out[8192,8192] fp32 : d2[n,m] = xn[n] + yn[m] - 2 * (xs @ ys^T)[n,m]
// xs = x*exp(ls), ys = y*exp(ls); xn,yn = row norms (kept exact in fp32).
// GEMM via classic mma.sync (sm_100 base target — tcgen05 unavailable, see R4).
// ============================================================================
#define NROWS   8192
#define D_DIM   512
#define TILE_M  128
#define TILE_N  128
#define KCHUNK  64                       // halves per stage = 128 B per row
#define NCHUNKS (D_DIM / KCHUNK)         // 8
#define A_TILE_BYTES (TILE_M * 128)      // 16384
#define B_TILE_BYTES (TILE_N * 128)      // 16384
#define STAGE_BYTES  (A_TILE_BYTES + B_TILE_BYTES)   // 32768
#define NSTAGES 3
#define GEMM_THREADS 256
#define SMEM_BYTES   (1024 + NSTAGES * STAGE_BYTES)  // align slack + 3 stages

// Scratch (device globals — no allocation allowed)
__device__ __align__(256) __half g_xh[(size_t)NROWS * D_DIM];
__device__ __align__(256) __half g_yh[(size_t)NROWS * D_DIM];
__device__ float g_xn[NROWS];
__device__ float g_yn[NROWS];

// ============================================================================
// Helpers
// ============================================================================
#define SW128(o) ((o) ^ (((o) >> 3) & 0x70))

__device__ __forceinline__ uint32_t smem_u32(const void* p) {
    uint32_t a;
    asm("{ .reg .u64 t; cvta.to.shared.u64 t, %1; cvt.u32.u64 %0, t; }"
        : "=r"(a) : "l"(p));
    return a;
}

__device__ __forceinline__ void cp_async16(uint32_t smem_addr, const void* gptr) {
    asm volatile("cp.async.cg.shared.global [%0], [%1], 16;\n"
                 :: "r"(smem_addr), "l"(gptr) : "memory");
}
#define CP_ASYNC_COMMIT() asm volatile("cp.async.commit_group;\n" ::: "memory")
#define CP_ASYNC_WAIT(n)  asm volatile("cp.async.wait_group %0;\n" :: "n"(n) : "memory")

__device__ __forceinline__ void ldsm_x4(uint32_t& r0, uint32_t& r1,
                                        uint32_t& r2, uint32_t& r3,
                                        uint32_t addr) {
    asm volatile("ldmatrix.sync.aligned.m8n8.x4.shared.b16 {%0,%1,%2,%3}, [%4];\n"
                 : "=r"(r0), "=r"(r1), "=r"(r2), "=r"(r3) : "r"(addr));
}

__device__ __forceinline__ void mma16816(float* c, const uint32_t* a,
                                         const uint32_t* b) {
    asm volatile(
        "mma.sync.aligned.m16n8k16.row.col.f32.f16.f16.f32 "
        "{%0,%1,%2,%3}, {%4,%5,%6,%7}, {%8,%9}, {%0,%1,%2,%3};\n"
        : "+f"(c[0]), "+f"(c[1]), "+f"(c[2]), "+f"(c[3])
        : "r"(a[0]), "r"(a[1]), "r"(a[2]), "r"(a[3]), "r"(b[0]), "r"(b[1]));
}

// ============================================================================
// Convert: xs = x * exp(log_scale) -> fp16; norms in fp32 (exact vs reference)
// ============================================================================
__global__ void __launch_bounds__(128)
convert_kernel(const float* __restrict__ src, const float* __restrict__ ls,
               int which) {
    __half* dst = which ? g_yh : g_xh;
    float*  nrm = which ? g_yn : g_xn;
    int row = blockIdx.x;
    int t = threadIdx.x;

    float4 lsv = reinterpret_cast<const float4*>(ls)[t];
    float4 v   = reinterpret_cast<const float4*>(src + (size_t)row * D_DIM)[t];
    v.x *= expf(lsv.x);
    v.y *= expf(lsv.y);
    v.z *= expf(lsv.z);
    v.w *= expf(lsv.w);

    float acc = v.x * v.x + v.y * v.y + v.z * v.z + v.w * v.w;

    __half2 h0 = __floats2half2_rn(v.x, v.y);
    __half2 h1 = __floats2half2_rn(v.z, v.w);
    uint2 pk;
    pk.x = *reinterpret_cast<uint32_t*>(&h0);
    pk.y = *reinterpret_cast<uint32_t*>(&h1);
    reinterpret_cast<uint2*>(dst + (size_t)row * D_DIM)[t] = pk;

    #pragma unroll
    for (int o = 16; o > 0; o >>= 1)
        acc += __shfl_xor_sync(0xFFFFFFFFu, acc, o);
    __shared__ float ws[4];
    if ((t & 31) == 0) ws[t >> 5] = acc;
    __syncthreads();
    if (t == 0) nrm[row] = ws[0] + ws[1] + ws[2] + ws[3];
}

// ============================================================================
// GEMM: 128x128 tile/CTA, 8 warps (2 M x 4 N), warp tile 64x32, K in 8 chunks
// of 64 halves, 3-stage cp.async pipeline, mma.sync m16n8k16 fp16->fp32.
// ============================================================================
__global__ void __launch_bounds__(GEMM_THREADS)
gemm_kernel(float* __restrict__ out) {
    extern __shared__ char dsm[];
    uint32_t raw   = smem_u32(dsm);
    uint32_t tiles = (raw + 1023u) & ~1023u;

    const int tid  = threadIdx.x;
    const int wid  = tid >> 5;
    const int lane = tid & 31;
    const int wm   = wid & 1;        // 0..1 -> 64-row block
    const int wn   = wid >> 1;       // 0..3 -> 32-col block

    const int m0 = blockIdx.y * TILE_M;
    const int n0 = blockIdx.x * TILE_N;
    const __half* gA = g_xh + (size_t)m0 * D_DIM;
    const __half* gB = g_yh + (size_t)n0 * D_DIM;

    // Per-lane ldmatrix offsets (relative to tile base; swizzle is base-invariant
    // because stage bases are 1024-aligned).
    // A: row = wm*64 + mi*16 + (lane&15), colByte = kk*32 + (lane>>4)*16
    // B: row = wn*32 + nb*16 + ((lane>>4)<<3) + (lane&7), colByte = kk*32 + ((lane>>3)&1)*16
    uint32_t a_off[4][4], b_off[4][2];
    #pragma unroll
    for (int kk = 0; kk < 4; ++kk) {
        #pragma unroll
        for (int mi = 0; mi < 4; ++mi) {
            uint32_t row = wm * 64 + mi * 16 + (lane & 15);
            uint32_t col = kk * 32 + (lane >> 4) * 16;
            a_off[kk][mi] = SW128(row * 128 + col);
        }
        #pragma unroll
        for (int nb = 0; nb < 2; ++nb) {
            uint32_t row = wn * 32 + nb * 16 + ((lane >> 4) << 3) + (lane & 7);
            uint32_t col = kk * 32 + ((lane >> 3) & 1) * 16;
            b_off[kk][nb] = SW128(row * 128 + col);
        }
    }

    float acc[4][4][4];
    #pragma unroll
    for (int mi = 0; mi < 4; ++mi)
        #pragma unroll
        for (int ni = 0; ni < 4; ++ni)
            #pragma unroll
            for (int e = 0; e < 4; ++e) acc[mi][ni][e] = 0.0f;

    // ---- stage fill: A 128x128B + B 128x128B via 16B cp.async, SW128 ----
    auto fill = [&](int c) {
        uint32_t abase = tiles + (c % NSTAGES) * STAGE_BYTES;
        uint32_t bbase = abase + A_TILE_BYTES;
        const char* ga = (const char*)(gA + c * KCHUNK);
        const char* gb = (const char*)(gB + c * KCHUNK);
        #pragma unroll
        for (int i = tid; i < 1024; i += GEMM_THREADS) {
            int row = i >> 3, seg = i & 7;
            uint32_t off = row * 128 + seg * 16;
            cp_async16(abase + SW128(off), ga + (size_t)row * (D_DIM * 2) + seg * 16);
        }
        #pragma unroll
        for (int i = tid; i < 1024; i += GEMM_THREADS) {
            int row = i >> 3, seg = i & 7;
            uint32_t off = row * 128 + seg * 16;
            cp_async16(bbase + SW128(off), gb + (size_t)row * (D_DIM * 2) + seg * 16);
        }
        CP_ASYNC_COMMIT();
    };

    fill(0);
    fill(1);

    #pragma unroll 1
    for (int c = 0; c < NCHUNKS; ++c) {
        if (c + 2 < NCHUNKS) fill(c + 2);
        if (c < NCHUNKS - 2)      CP_ASYNC_WAIT(2);
        else if (c == NCHUNKS - 2) CP_ASYNC_WAIT(1);
        else                       CP_ASYNC_WAIT(0);
        __syncthreads();

        uint32_t abase = tiles + (c % NSTAGES) * STAGE_BYTES;
        uint32_t bbase = abase + A_TILE_BYTES;

        #pragma unroll
        for (int kk = 0; kk < 4; ++kk) {
            uint32_t a[4][4];
            uint32_t b[4][2];
            #pragma unroll
            for (int mi = 0; mi < 4; ++mi)
                ldsm_x4(a[mi][0], a[mi][1], a[mi][2], a[mi][3],
                        abase + a_off[kk][mi]);
            #pragma unroll
            for (int nb = 0; nb < 2; ++nb) {
                uint32_t r0, r1, r2, r3;
                ldsm_x4(r0, r1, r2, r3, bbase + b_off[kk][nb]);
                b[2 * nb][0] = r0;  b[2 * nb][1] = r1;       // n8 block 2nb
                b[2 * nb + 1][0] = r2;  b[2 * nb + 1][1] = r3; // n8 block 2nb+1
            }
            #pragma unroll
            for (int mi = 0; mi < 4; ++mi)
                #pragma unroll
                for (int ni = 0; ni < 4; ++ni)
                    mma16816(acc[mi][ni], a[mi], b[ni]);
        }
        __syncthreads();
    }

    // ---- epilogue: d2 = xn[r] + yn[c] - 2*acc, float2 streaming stores ----
    const int row_base = m0 + wm * 64;
    const int col_base = n0 + wn * 32;
    const int gr = lane >> 2;           // 0..7
    const int cp = (lane & 3) * 2;      // 0,2,4,6

    float yv[4][2];
    #pragma unroll
    for (int ni = 0; ni < 4; ++ni) {
        yv[ni][0] = __ldg(&g_yn[col_base + ni * 8 + cp]);
        yv[ni][1] = __ldg(&g_yn[col_base + ni * 8 + cp + 1]);
    }

    #pragma unroll
    for (int mi = 0; mi < 4; ++mi) {
        #pragma unroll
        for (int h = 0; h < 2; ++h) {
            int r = row_base + mi * 16 + gr + h * 8;
            float xr = __ldg(&g_xn[r]);
            float* orow = out + (size_t)r * NROWS + col_base;
            #pragma unroll
            for (int ni = 0; ni < 4; ++ni) {
                float2 o;
                o.x = xr + yv[ni][0] - 2.0f * acc[mi][ni][h * 2 + 0];
                o.y = xr + yv[ni][1] - 2.0f * acc[mi][ni][h * 2 + 1];
                __stcs(reinterpret_cast<float2*>(orow + ni * 8 + cp), o);
            }
        }
    }
}

// ============================================================================
// kernel_launch
// ============================================================================
extern "C" void kernel_launch(void* const* d_in, const int* in_sizes, int n_in,
                              void* d_out, int out_size) {
    const float* x  = (const float*)d_in[0];
    const float* y  = (const float*)d_in[1];
    const float* ls = (const float*)d_in[2];
    float* out = (float*)d_out;

    convert_kernel<<<NROWS, 128>>>(x, ls, 0);
    convert_kernel<<<NROWS, 128>>>(y, ls, 1);

    cudaFuncSetAttribute(gemm_kernel,
                         cudaFuncAttributeMaxDynamicSharedMemorySize, SMEM_BYTES);
    dim3 grid(NROWS / TILE_N, NROWS / TILE_M);
    gemm_kernel<<<grid, GEMM_THREADS, SMEM_BYTES>>>(out);
}

// round 6
// speedup vs baseline: 1.0003x; 1.0003x over previous
#include <cuda_runtime.h>
#include <cuda_fp16.h>
#include <cstdint>

// ============================================================================
// DiagonalMahalanobisDistance: x[8192,512], y[8192,512], log_scale[512] (fp32)
// out[8192,8192] fp32 : d2[n,m] = xn[n] + yn[m] - 2 * (xs @ ys^T)[n,m]
// xs = x*exp(ls), ys = y*exp(ls); xn,yn = row norms (kept exact in fp32).
// GEMM via classic mma.sync (sm_100 base target — tcgen05 unavailable, see R4).
// ============================================================================
#define NROWS   8192
#define D_DIM   512
#define TILE_M  128
#define TILE_N  128
#define KCHUNK  64                       // halves per stage = 128 B per row
#define NCHUNKS (D_DIM / KCHUNK)         // 8
#define A_TILE_BYTES (TILE_M * 128)      // 16384
#define B_TILE_BYTES (TILE_N * 128)      // 16384
#define STAGE_BYTES  (A_TILE_BYTES + B_TILE_BYTES)   // 32768
#define NSTAGES 3
#define GEMM_THREADS 256
#define SMEM_BYTES   (1024 + NSTAGES * STAGE_BYTES)  // align slack + 3 stages

// Scratch (device globals — no allocation allowed)
__device__ __align__(256) __half g_xh[(size_t)NROWS * D_DIM];
__device__ __align__(256) __half g_yh[(size_t)NROWS * D_DIM];
__device__ float g_xn[NROWS];
__device__ float g_yn[NROWS];

// ============================================================================
// Helpers
// ============================================================================
#define SW128(o) ((o) ^ (((o) >> 3) & 0x70))

__device__ __forceinline__ uint32_t smem_u32(const void* p) {
    uint32_t a;
    asm("{ .reg .u64 t; cvta.to.shared.u64 t, %1; cvt.u32.u64 %0, t; }"
        : "=r"(a) : "l"(p));
    return a;
}

__device__ __forceinline__ void cp_async16(uint32_t smem_addr, const void* gptr) {
    asm volatile("cp.async.cg.shared.global [%0], [%1], 16;\n"
                 :: "r"(smem_addr), "l"(gptr) : "memory");
}
#define CP_ASYNC_COMMIT() asm volatile("cp.async.commit_group;\n" ::: "memory")
#define CP_ASYNC_WAIT(n)  asm volatile("cp.async.wait_group %0;\n" :: "n"(n) : "memory")

__device__ __forceinline__ void ldsm_x4(uint32_t& r0, uint32_t& r1,
                                        uint32_t& r2, uint32_t& r3,
                                        uint32_t addr) {
    asm volatile("ldmatrix.sync.aligned.m8n8.x4.shared.b16 {%0,%1,%2,%3}, [%4];\n"
                 : "=r"(r0), "=r"(r1), "=r"(r2), "=r"(r3) : "r"(addr));
}

__device__ __forceinline__ void mma16816(float* c, const uint32_t* a,
                                         const uint32_t* b) {
    asm volatile(
        "mma.sync.aligned.m16n8k16.row.col.f32.f16.f16.f32 "
        "{%0,%1,%2,%3}, {%4,%5,%6,%7}, {%8,%9}, {%0,%1,%2,%3};\n"
        : "+f"(c[0]), "+f"(c[1]), "+f"(c[2]), "+f"(c[3])
        : "r"(a[0]), "r"(a[1]), "r"(a[2]), "r"(a[3]), "r"(b[0]), "r"(b[1]));
}

// ============================================================================
// Convert: xs = x * exp(log_scale) -> fp16; norms in fp32 (exact vs reference)
// ============================================================================
__global__ void __launch_bounds__(128)
convert_kernel(const float* __restrict__ src, const float* __restrict__ ls,
               int which) {
    __half* dst = which ? g_yh : g_xh;
    float*  nrm = which ? g_yn : g_xn;
    int row = blockIdx.x;
    int t = threadIdx.x;

    float4 lsv = reinterpret_cast<const float4*>(ls)[t];
    float4 v   = reinterpret_cast<const float4*>(src + (size_t)row * D_DIM)[t];
    v.x *= expf(lsv.x);
    v.y *= expf(lsv.y);
    v.z *= expf(lsv.z);
    v.w *= expf(lsv.w);

    float acc = v.x * v.x + v.y * v.y + v.z * v.z + v.w * v.w;

    __half2 h0 = __floats2half2_rn(v.x, v.y);
    __half2 h1 = __floats2half2_rn(v.z, v.w);
    uint2 pk;
    pk.x = *reinterpret_cast<uint32_t*>(&h0);
    pk.y = *reinterpret_cast<uint32_t*>(&h1);
    reinterpret_cast<uint2*>(dst + (size_t)row * D_DIM)[t] = pk;

    #pragma unroll
    for (int o = 16; o > 0; o >>= 1)
        acc += __shfl_xor_sync(0xFFFFFFFFu, acc, o);
    __shared__ float ws[4];
    if ((t & 31) == 0) ws[t >> 5] = acc;
    __syncthreads();
    if (t == 0) nrm[row] = ws[0] + ws[1] + ws[2] + ws[3];
}

// ============================================================================
// GEMM: 128x128 tile/CTA, 8 warps (2 M x 4 N), warp tile 64x32, K in 8 chunks
// of 64 halves, 3-stage cp.async pipeline, mma.sync m16n8k16 fp16->fp32.
// ============================================================================
__global__ void __launch_bounds__(GEMM_THREADS)
gemm_kernel(float* __restrict__ out) {
    extern __shared__ char dsm[];
    uint32_t raw   = smem_u32(dsm);
    uint32_t tiles = (raw + 1023u) & ~1023u;

    const int tid  = threadIdx.x;
    const int wid  = tid >> 5;
    const int lane = tid & 31;
    const int wm   = wid & 1;        // 0..1 -> 64-row block
    const int wn   = wid >> 1;       // 0..3 -> 32-col block

    const int m0 = blockIdx.y * TILE_M;
    const int n0 = blockIdx.x * TILE_N;
    const __half* gA = g_xh + (size_t)m0 * D_DIM;
    const __half* gB = g_yh + (size_t)n0 * D_DIM;

    // Per-lane ldmatrix offsets (relative to tile base; swizzle is base-invariant
    // because stage bases are 1024-aligned).
    // A: row = wm*64 + mi*16 + (lane&15), colByte = kk*32 + (lane>>4)*16
    // B: row = wn*32 + nb*16 + ((lane>>4)<<3) + (lane&7), colByte = kk*32 + ((lane>>3)&1)*16
    uint32_t a_off[4][4], b_off[4][2];
    #pragma unroll
    for (int kk = 0; kk < 4; ++kk) {
        #pragma unroll
        for (int mi = 0; mi < 4; ++mi) {
            uint32_t row = wm * 64 + mi * 16 + (lane & 15);
            uint32_t col = kk * 32 + (lane >> 4) * 16;
            a_off[kk][mi] = SW128(row * 128 + col);
        }
        #pragma unroll
        for (int nb = 0; nb < 2; ++nb) {
            uint32_t row = wn * 32 + nb * 16 + ((lane >> 4) << 3) + (lane & 7);
            uint32_t col = kk * 32 + ((lane >> 3) & 1) * 16;
            b_off[kk][nb] = SW128(row * 128 + col);
        }
    }

    float acc[4][4][4];
    #pragma unroll
    for (int mi = 0; mi < 4; ++mi)
        #pragma unroll
        for (int ni = 0; ni < 4; ++ni)
            #pragma unroll
            for (int e = 0; e < 4; ++e) acc[mi][ni][e] = 0.0f;

    // ---- stage fill: A 128x128B + B 128x128B via 16B cp.async, SW128 ----
    auto fill = [&](int c) {
        uint32_t abase = tiles + (c % NSTAGES) * STAGE_BYTES;
        uint32_t bbase = abase + A_TILE_BYTES;
        const char* ga = (const char*)(gA + c * KCHUNK);
        const char* gb = (const char*)(gB + c * KCHUNK);
        #pragma unroll
        for (int i = tid; i < 1024; i += GEMM_THREADS) {
            int row = i >> 3, seg = i & 7;
            uint32_t off = row * 128 + seg * 16;
            cp_async16(abase + SW128(off), ga + (size_t)row * (D_DIM * 2) + seg * 16);
        }
        #pragma unroll
        for (int i = tid; i < 1024; i += GEMM_THREADS) {
            int row = i >> 3, seg = i & 7;
            uint32_t off = row * 128 + seg * 16;
            cp_async16(bbase + SW128(off), gb + (size_t)row * (D_DIM * 2) + seg * 16);
        }
        CP_ASYNC_COMMIT();
    };

    fill(0);
    fill(1);

    #pragma unroll 1
    for (int c = 0; c < NCHUNKS; ++c) {
        if (c + 2 < NCHUNKS) fill(c + 2);
        if (c < NCHUNKS - 2)      CP_ASYNC_WAIT(2);
        else if (c == NCHUNKS - 2) CP_ASYNC_WAIT(1);
        else                       CP_ASYNC_WAIT(0);
        __syncthreads();

        uint32_t abase = tiles + (c % NSTAGES) * STAGE_BYTES;
        uint32_t bbase = abase + A_TILE_BYTES;

        #pragma unroll
        for (int kk = 0; kk < 4; ++kk) {
            uint32_t a[4][4];
            uint32_t b[4][2];
            #pragma unroll
            for (int mi = 0; mi < 4; ++mi)
                ldsm_x4(a[mi][0], a[mi][1], a[mi][2], a[mi][3],
                        abase + a_off[kk][mi]);
            #pragma unroll
            for (int nb = 0; nb < 2; ++nb) {
                uint32_t r0, r1, r2, r3;
                ldsm_x4(r0, r1, r2, r3, bbase + b_off[kk][nb]);
                b[2 * nb][0] = r0;  b[2 * nb][1] = r1;       // n8 block 2nb
                b[2 * nb + 1][0] = r2;  b[2 * nb + 1][1] = r3; // n8 block 2nb+1
            }
            #pragma unroll
            for (int mi = 0; mi < 4; ++mi)
                #pragma unroll
                for (int ni = 0; ni < 4; ++ni)
                    mma16816(acc[mi][ni], a[mi], b[ni]);
        }
        __syncthreads();
    }

    // ---- epilogue: d2 = xn[r] + yn[c] - 2*acc, float2 streaming stores ----
    const int row_base = m0 + wm * 64;
    const int col_base = n0 + wn * 32;
    const int gr = lane >> 2;           // 0..7
    const int cp = (lane & 3) * 2;      // 0,2,4,6

    float yv[4][2];
    #pragma unroll
    for (int ni = 0; ni < 4; ++ni) {
        yv[ni][0] = __ldg(&g_yn[col_base + ni * 8 + cp]);
        yv[ni][1] = __ldg(&g_yn[col_base + ni * 8 + cp + 1]);
    }

    #pragma unroll
    for (int mi = 0; mi < 4; ++mi) {
        #pragma unroll
        for (int h = 0; h < 2; ++h) {
            int r = row_base + mi * 16 + gr + h * 8;
            float xr = __ldg(&g_xn[r]);
            float* orow = out + (size_t)r * NROWS + col_base;
            #pragma unroll
            for (int ni = 0; ni < 4; ++ni) {
                float2 o;
                o.x = xr + yv[ni][0] - 2.0f * acc[mi][ni][h * 2 + 0];
                o.y = xr + yv[ni][1] - 2.0f * acc[mi][ni][h * 2 + 1];
                __stcs(reinterpret_cast<float2*>(orow + ni * 8 + cp), o);
            }
        }
    }
}

// ============================================================================
// kernel_launch
// ============================================================================
extern "C" void kernel_launch(void* const* d_in, const int* in_sizes, int n_in,
                              void* d_out, int out_size) {
    const float* x  = (const float*)d_in[0];
    const float* y  = (const float*)d_in[1];
    const float* ls = (const float*)d_in[2];
    float* out = (float*)d_out;

    convert_kernel<<<NROWS, 128>>>(x, ls, 0);
    convert_kernel<<<NROWS, 128>>>(y, ls, 1);

    cudaFuncSetAttribute(gemm_kernel,
                         cudaFuncAttributeMaxDynamicSharedMemorySize, SMEM_BYTES);
    dim3 grid(NROWS / TILE_N, NROWS / TILE_M);
    gemm_kernel<<<grid, GEMM_THREADS, SMEM_BYTES>>>(out);
}

// round 7
// speedup vs baseline: 1.0029x; 1.0026x over previous
#include <cuda_runtime.h>
#include <cuda_fp16.h>
#include <cstdint>

// ============================================================================
// DiagonalMahalanobisDistance: x[8192,512], y[8192,512], log_scale[512] (fp32)
// out[8192,8192] fp32 : d2[n,m] = xn[n] + yn[m] - 2 * (xs @ ys^T)[n,m]
// xs = x*exp(ls), ys = y*exp(ls); xn,yn = row norms (kept exact in fp32).
// GEMM via classic mma.sync (sm_100 base target — tcgen05 unavailable, see R4).
// ============================================================================
#define NROWS   8192
#define D_DIM   512
#define TILE_M  128
#define TILE_N  128
#define KCHUNK  64                       // halves per stage = 128 B per row
#define NCHUNKS (D_DIM / KCHUNK)         // 8
#define A_TILE_BYTES (TILE_M * 128)      // 16384
#define B_TILE_BYTES (TILE_N * 128)      // 16384
#define STAGE_BYTES  (A_TILE_BYTES + B_TILE_BYTES)   // 32768
#define NSTAGES 3
#define GEMM_THREADS 256
#define SMEM_BYTES   (1024 + NSTAGES * STAGE_BYTES)  // align slack + 3 stages

// Scratch (device globals — no allocation allowed)
__device__ __align__(256) __half g_xh[(size_t)NROWS * D_DIM];
__device__ __align__(256) __half g_yh[(size_t)NROWS * D_DIM];
__device__ float g_xn[NROWS];
__device__ float g_yn[NROWS];

// ============================================================================
// Helpers
// ============================================================================
#define SW128(o) ((o) ^ (((o) >> 3) & 0x70))

__device__ __forceinline__ uint32_t smem_u32(const void* p) {
    uint32_t a;
    asm("{ .reg .u64 t; cvta.to.shared.u64 t, %1; cvt.u32.u64 %0, t; }"
        : "=r"(a) : "l"(p));
    return a;
}

__device__ __forceinline__ void cp_async16(uint32_t smem_addr, const void* gptr) {
    asm volatile("cp.async.cg.shared.global [%0], [%1], 16;\n"
                 :: "r"(smem_addr), "l"(gptr) : "memory");
}
#define CP_ASYNC_COMMIT() asm volatile("cp.async.commit_group;\n" ::: "memory")
#define CP_ASYNC_WAIT(n)  asm volatile("cp.async.wait_group %0;\n" :: "n"(n) : "memory")

__device__ __forceinline__ void ldsm_x4(uint32_t& r0, uint32_t& r1,
                                        uint32_t& r2, uint32_t& r3,
                                        uint32_t addr) {
    asm volatile("ldmatrix.sync.aligned.m8n8.x4.shared.b16 {%0,%1,%2,%3}, [%4];\n"
                 : "=r"(r0), "=r"(r1), "=r"(r2), "=r"(r3) : "r"(addr));
}

__device__ __forceinline__ void mma16816(float* c, const uint32_t* a,
                                         const uint32_t* b) {
    asm volatile(
        "mma.sync.aligned.m16n8k16.row.col.f32.f16.f16.f32 "
        "{%0,%1,%2,%3}, {%4,%5,%6,%7}, {%8,%9}, {%0,%1,%2,%3};\n"
        : "+f"(c[0]), "+f"(c[1]), "+f"(c[2]), "+f"(c[3])
        : "r"(a[0]), "r"(a[1]), "r"(a[2]), "r"(a[3]), "r"(b[0]), "r"(b[1]));
}

// ============================================================================
// Convert: xs = x * exp(log_scale) -> fp16; norms in fp32 (exact vs reference)
// ============================================================================
__global__ void __launch_bounds__(128)
convert_kernel(const float* __restrict__ src, const float* __restrict__ ls,
               int which) {
    __half* dst = which ? g_yh : g_xh;
    float*  nrm = which ? g_yn : g_xn;
    int row = blockIdx.x;
    int t = threadIdx.x;

    float4 lsv = reinterpret_cast<const float4*>(ls)[t];
    float4 v   = reinterpret_cast<const float4*>(src + (size_t)row * D_DIM)[t];
    v.x *= expf(lsv.x);
    v.y *= expf(lsv.y);
    v.z *= expf(lsv.z);
    v.w *= expf(lsv.w);

    float acc = v.x * v.x + v.y * v.y + v.z * v.z + v.w * v.w;

    __half2 h0 = __floats2half2_rn(v.x, v.y);
    __half2 h1 = __floats2half2_rn(v.z, v.w);
    uint2 pk;
    pk.x = *reinterpret_cast<uint32_t*>(&h0);
    pk.y = *reinterpret_cast<uint32_t*>(&h1);
    reinterpret_cast<uint2*>(dst + (size_t)row * D_DIM)[t] = pk;

    #pragma unroll
    for (int o = 16; o > 0; o >>= 1)
        acc += __shfl_xor_sync(0xFFFFFFFFu, acc, o);
    __shared__ float ws[4];
    if ((t & 31) == 0) ws[t >> 5] = acc;
    __syncthreads();
    if (t == 0) nrm[row] = ws[0] + ws[1] + ws[2] + ws[3];
}

// ============================================================================
// GEMM: 128x128 tile/CTA, 8 warps (2 M x 4 N), warp tile 64x32, K in 8 chunks
// of 64 halves, 3-stage cp.async pipeline, mma.sync m16n8k16 fp16->fp32.
// ============================================================================
__global__ void __launch_bounds__(GEMM_THREADS)
gemm_kernel(float* __restrict__ out) {
    extern __shared__ char dsm[];
    uint32_t raw   = smem_u32(dsm);
    uint32_t tiles = (raw + 1023u) & ~1023u;

    const int tid  = threadIdx.x;
    const int wid  = tid >> 5;
    const int lane = tid & 31;
    const int wm   = wid & 1;        // 0..1 -> 64-row block
    const int wn   = wid >> 1;       // 0..3 -> 32-col block

    const int m0 = blockIdx.y * TILE_M;
    const int n0 = blockIdx.x * TILE_N;
    const __half* gA = g_xh + (size_t)m0 * D_DIM;
    const __half* gB = g_yh + (size_t)n0 * D_DIM;

    // Per-lane ldmatrix offsets (relative to tile base; swizzle is base-invariant
    // because stage bases are 1024-aligned).
    // A: row = wm*64 + mi*16 + (lane&15), colByte = kk*32 + (lane>>4)*16
    // B: row = wn*32 + nb*16 + ((lane>>4)<<3) + (lane&7), colByte = kk*32 + ((lane>>3)&1)*16
    uint32_t a_off[4][4], b_off[4][2];
    #pragma unroll
    for (int kk = 0; kk < 4; ++kk) {
        #pragma unroll
        for (int mi = 0; mi < 4; ++mi) {
            uint32_t row = wm * 64 + mi * 16 + (lane & 15);
            uint32_t col = kk * 32 + (lane >> 4) * 16;
            a_off[kk][mi] = SW128(row * 128 + col);
        }
        #pragma unroll
        for (int nb = 0; nb < 2; ++nb) {
            uint32_t row = wn * 32 + nb * 16 + ((lane >> 4) << 3) + (lane & 7);
            uint32_t col = kk * 32 + ((lane >> 3) & 1) * 16;
            b_off[kk][nb] = SW128(row * 128 + col);
        }
    }

    float acc[4][4][4];
    #pragma unroll
    for (int mi = 0; mi < 4; ++mi)
        #pragma unroll
        for (int ni = 0; ni < 4; ++ni)
            #pragma unroll
            for (int e = 0; e < 4; ++e) acc[mi][ni][e] = 0.0f;

    // ---- stage fill: A 128x128B + B 128x128B via 16B cp.async, SW128 ----
    auto fill = [&](int c) {
        uint32_t abase = tiles + (c % NSTAGES) * STAGE_BYTES;
        uint32_t bbase = abase + A_TILE_BYTES;
        const char* ga = (const char*)(gA + c * KCHUNK);
        const char* gb = (const char*)(gB + c * KCHUNK);
        #pragma unroll
        for (int i = tid; i < 1024; i += GEMM_THREADS) {
            int row = i >> 3, seg = i & 7;
            uint32_t off = row * 128 + seg * 16;
            cp_async16(abase + SW128(off), ga + (size_t)row * (D_DIM * 2) + seg * 16);
        }
        #pragma unroll
        for (int i = tid; i < 1024; i += GEMM_THREADS) {
            int row = i >> 3, seg = i & 7;
            uint32_t off = row * 128 + seg * 16;
            cp_async16(bbase + SW128(off), gb + (size_t)row * (D_DIM * 2) + seg * 16);
        }
        CP_ASYNC_COMMIT();
    };

    fill(0);
    fill(1);

    #pragma unroll 1
    for (int c = 0; c < NCHUNKS; ++c) {
        if (c + 2 < NCHUNKS) fill(c + 2);
        if (c < NCHUNKS - 2)      CP_ASYNC_WAIT(2);
        else if (c == NCHUNKS - 2) CP_ASYNC_WAIT(1);
        else                       CP_ASYNC_WAIT(0);
        __syncthreads();

        uint32_t abase = tiles + (c % NSTAGES) * STAGE_BYTES;
        uint32_t bbase = abase + A_TILE_BYTES;

        #pragma unroll
        for (int kk = 0; kk < 4; ++kk) {
            uint32_t a[4][4];
            uint32_t b[4][2];
            #pragma unroll
            for (int mi = 0; mi < 4; ++mi)
                ldsm_x4(a[mi][0], a[mi][1], a[mi][2], a[mi][3],
                        abase + a_off[kk][mi]);
            #pragma unroll
            for (int nb = 0; nb < 2; ++nb) {
                uint32_t r0, r1, r2, r3;
                ldsm_x4(r0, r1, r2, r3, bbase + b_off[kk][nb]);
                b[2 * nb][0] = r0;  b[2 * nb][1] = r1;       // n8 block 2nb
                b[2 * nb + 1][0] = r2;  b[2 * nb + 1][1] = r3; // n8 block 2nb+1
            }
            #pragma unroll
            for (int mi = 0; mi < 4; ++mi)
                #pragma unroll
                for (int ni = 0; ni < 4; ++ni)
                    mma16816(acc[mi][ni], a[mi], b[ni]);
        }
        __syncthreads();
    }

    // ---- epilogue: d2 = xn[r] + yn[c] - 2*acc, float2 streaming stores ----
    const int row_base = m0 + wm * 64;
    const int col_base = n0 + wn * 32;
    const int gr = lane >> 2;           // 0..7
    const int cp = (lane & 3) * 2;      // 0,2,4,6

    float yv[4][2];
    #pragma unroll
    for (int ni = 0; ni < 4; ++ni) {
        yv[ni][0] = __ldg(&g_yn[col_base + ni * 8 + cp]);
        yv[ni][1] = __ldg(&g_yn[col_base + ni * 8 + cp + 1]);
    }

    #pragma unroll
    for (int mi = 0; mi < 4; ++mi) {
        #pragma unroll
        for (int h = 0; h < 2; ++h) {
            int r = row_base + mi * 16 + gr + h * 8;
            float xr = __ldg(&g_xn[r]);
            float* orow = out + (size_t)r * NROWS + col_base;
            #pragma unroll
            for (int ni = 0; ni < 4; ++ni) {
                float2 o;
                o.x = xr + yv[ni][0] - 2.0f * acc[mi][ni][h * 2 + 0];
                o.y = xr + yv[ni][1] - 2.0f * acc[mi][ni][h * 2 + 1];
                __stcs(reinterpret_cast<float2*>(orow + ni * 8 + cp), o);
            }
        }
    }
}

// ============================================================================
// kernel_launch
// ============================================================================
extern "C" void kernel_launch(void* const* d_in, const int* in_sizes, int n_in,
                              void* d_out, int out_size) {
    const float* x  = (const float*)d_in[0];
    const float* y  = (const float*)d_in[1];
    const float* ls = (const float*)d_in[2];
    float* out = (float*)d_out;

    convert_kernel<<<NROWS, 128>>>(x, ls, 0);
    convert_kernel<<<NROWS, 128>>>(y, ls, 1);

    cudaFuncSetAttribute(gemm_kernel,
                         cudaFuncAttributeMaxDynamicSharedMemorySize, SMEM_BYTES);
    dim3 grid(NROWS / TILE_N, NROWS / TILE_M);
    gemm_kernel<<<grid, GEMM_THREADS, SMEM_BYTES>>>(out);
}